// round 3
// baseline (speedup 1.0000x reference)
#include <cuda_runtime.h>
#include <math.h>

#define N_NODES 50000
#define N_EDGES 800000

// ---- scratch (device globals; no allocation allowed) ----
__device__ __align__(16) float g_h1[N_NODES * 256];
__device__ __align__(16) float g_h2[N_NODES * 256];
__device__ __align__(16) float g_z [N_NODES * 256];   // also holds layer0's (A+D)x
__device__ float g_sim[N_EDGES];          // CSR order
__device__ int   g_ccol[N_EDGES];         // CSR order
__device__ float g_rnrm[N_NODES];
__device__ float g_irs[N_NODES];
__device__ float g_wself[N_NODES];
__device__ int   g_rowptr[N_NODES + 1];
__device__ int   g_wr[N_NODES];
__device__ int   g_cnt[N_NODES];

// ================= CSR build (row/col fixed across the 3 layers) =============
__global__ void k_zero_cnt() {
    int i = blockIdx.x * blockDim.x + threadIdx.x;
    if (i < N_NODES) g_cnt[i] = 0;
}

__global__ void k_hist(const int* __restrict__ row) {
    for (int e = blockIdx.x * blockDim.x + threadIdx.x; e < N_EDGES;
         e += gridDim.x * blockDim.x)
        atomicAdd(&g_cnt[row[e]], 1);
}

// single-block exclusive scan over 50000 counts
__global__ void k_scan() {
    __shared__ int wsum[32];
    __shared__ int carry;
    int tid = threadIdx.x, lane = tid & 31, wid = tid >> 5;
    if (tid == 0) carry = 0;
    __syncthreads();
    for (int base = 0; base < N_NODES; base += 1024) {
        int i = base + tid;
        int v = (i < N_NODES) ? g_cnt[i] : 0;
        int inc = v;
#pragma unroll
        for (int o = 1; o < 32; o <<= 1) {
            int y = __shfl_up_sync(0xffffffffu, inc, o);
            if (lane >= o) inc += y;
        }
        if (lane == 31) wsum[wid] = inc;
        __syncthreads();
        if (wid == 0) {
            int w = wsum[lane];
#pragma unroll
            for (int o = 1; o < 32; o <<= 1) {
                int y = __shfl_up_sync(0xffffffffu, w, o);
                if (lane >= o) w += y;
            }
            wsum[lane] = w;
        }
        __syncthreads();
        int pre = (wid > 0) ? wsum[wid - 1] : 0;
        int excl = carry + pre + inc - v;
        if (i < N_NODES) { g_rowptr[i] = excl; g_wr[i] = excl; }
        int chunk_total = wsum[31];
        __syncthreads();
        if (tid == 0) carry += chunk_total;
        __syncthreads();
    }
    if (tid == 0) g_rowptr[N_NODES] = carry;
}

__global__ void k_scatter(const int* __restrict__ row, const int* __restrict__ col) {
    for (int e = blockIdx.x * blockDim.x + threadIdx.x; e < N_EDGES;
         e += gridDim.x * blockDim.x) {
        int p = atomicAdd(&g_wr[row[e]], 1);
        g_ccol[p] = col[e];
    }
}

// ================= per-layer kernels =========================================
// reciprocal node norms
template <int IN>
__global__ void k_norms(const float* __restrict__ x) {
    int n = (blockIdx.x * blockDim.x + threadIdx.x) >> 5;
    if (n >= N_NODES) return;
    int lane = threadIdx.x & 31;
    const float4* xr = (const float4*)(x + (size_t)n * IN);
    float s = 0.0f;
#pragma unroll
    for (int i = 0; i < IN / 128; i++) {
        float4 v = xr[lane + 32 * i];
        s += v.x * v.x + v.y * v.y + v.z * v.z + v.w * v.w;
    }
#pragma unroll
    for (int o = 16; o; o >>= 1) s += __shfl_xor_sync(0xffffffffu, s, o);
    if (lane == 0) g_rnrm[n] = 1.0f / fmaxf(sqrtf(s), 1e-12f);
}

// fused SDDMM + rowsum + degree: warp per node, row held in registers.
// Writes thresholded sim in CSR order, g_irs, g_wself.
template <int IN>
__global__ void k_simfused(const float* __restrict__ x) {
    int n = (blockIdx.x * blockDim.x + threadIdx.x) >> 5;
    if (n >= N_NODES) return;
    int lane = threadIdx.x & 31;
    constexpr int V = IN / 128;
    float4 a[V];
    const float4* xr = (const float4*)(x + (size_t)n * IN);
#pragma unroll
    for (int i = 0; i < V; i++) a[i] = xr[lane + 32 * i];
    float rn = g_rnrm[n];
    int b = g_rowptr[n], e2 = g_rowptr[n + 1];
    float rowsum = 0.0f;
    int cnt = 0;
    int j = b;
    for (; j + 2 <= e2; j += 2) {
        int c0 = g_ccol[j], c1 = g_ccol[j + 1];
        const float4* xb0 = (const float4*)(x + (size_t)c0 * IN);
        const float4* xb1 = (const float4*)(x + (size_t)c1 * IN);
        float s0 = 0.0f, s1 = 0.0f;
#pragma unroll
        for (int i = 0; i < V; i++) {
            float4 v0 = xb0[lane + 32 * i];
            float4 v1 = xb1[lane + 32 * i];
            s0 += a[i].x * v0.x + a[i].y * v0.y + a[i].z * v0.z + a[i].w * v0.w;
            s1 += a[i].x * v1.x + a[i].y * v1.y + a[i].z * v1.z + a[i].w * v1.w;
        }
#pragma unroll
        for (int o = 16; o; o >>= 1) {
            s0 += __shfl_xor_sync(0xffffffffu, s0, o);
            s1 += __shfl_xor_sync(0xffffffffu, s1, o);
        }
        float sim0 = s0 * rn * g_rnrm[c0];
        float sim1 = s1 * rn * g_rnrm[c1];
        sim0 = (sim0 < 0.1f) ? 0.0f : sim0;
        sim1 = (sim1 < 0.1f) ? 0.0f : sim1;
        rowsum += sim0 + sim1;
        cnt += (sim0 != 0.0f) + (sim1 != 0.0f);
        if (lane == 0) { g_sim[j] = sim0; g_sim[j + 1] = sim1; }
    }
    if (j < e2) {
        int c0 = g_ccol[j];
        const float4* xb0 = (const float4*)(x + (size_t)c0 * IN);
        float s0 = 0.0f;
#pragma unroll
        for (int i = 0; i < V; i++) {
            float4 v0 = xb0[lane + 32 * i];
            s0 += a[i].x * v0.x + a[i].y * v0.y + a[i].z * v0.z + a[i].w * v0.w;
        }
#pragma unroll
        for (int o = 16; o; o >>= 1) s0 += __shfl_xor_sync(0xffffffffu, s0, o);
        float sim0 = s0 * rn * g_rnrm[c0];
        sim0 = (sim0 < 0.1f) ? 0.0f : sim0;
        rowsum += sim0;
        cnt += (sim0 != 0.0f);
        if (lane == 0) g_sim[j] = sim0;
    }
    if (lane == 0) {
        g_irs[n] = (rowsum > 0.0f) ? (1.0f / rowsum) : 0.0f;
        g_wself[n] = expf(1.0f / (float)(cnt + 1));
    }
}

// ====== 8x8 register-tiled SGEMM, one head per blockIdx.y ======
// Z[n, h*64+o] = sum_d X[n,d] * W[h,d,o]; optional fused leaky-relu.
template <int IN, bool RELU>
__global__ void __launch_bounds__(128) k_gemm8(const float* __restrict__ X,
                                               const float* __restrict__ W,
                                               float* __restrict__ Z,
                                               int OUTF) {
    constexpr int BM = 128, BN = 64, BK = 16;
    __shared__ float sXT[BK][BM + 4];
    __shared__ float sW[BK][BN + 4];
    int tid = threadIdx.x;
    int n0 = blockIdx.x * BM;
    int h = blockIdx.y;
    int f0 = h * BN;
    int tx = tid & 7, ty = tid >> 3;     // 8 x 16
    float acc[8][8];
#pragma unroll
    for (int i = 0; i < 8; i++)
#pragma unroll
        for (int jj = 0; jj < 8; jj++) acc[i][jj] = 0.0f;

    for (int k0 = 0; k0 < IN; k0 += BK) {
        {   // X tile: row tid, 16 d values, transposed
            int n = n0 + tid;
#pragma unroll
            for (int i = 0; i < 4; i++) {
                float4 v = (n < N_NODES)
                               ? *(const float4*)&X[(size_t)n * IN + k0 + i * 4]
                               : make_float4(0.f, 0.f, 0.f, 0.f);
                sXT[i * 4 + 0][tid] = v.x;
                sXT[i * 4 + 1][tid] = v.y;
                sXT[i * 4 + 2][tid] = v.z;
                sXT[i * 4 + 3][tid] = v.w;
            }
        }
        {   // W tile: 16 x 64 = 256 float4 / 128 threads
#pragma unroll
            for (int t = 0; t < 2; t++) {
                int idx = tid + t * 128;
                int kk = idx >> 4, f4 = (idx & 15) * 4;
                *(float4*)&sW[kk][f4] =
                    *(const float4*)&W[((size_t)h * IN + k0 + kk) * 64 + f4];
            }
        }
        __syncthreads();
#pragma unroll
        for (int k = 0; k < BK; k++) {
            float av[8], bv[8];
            *(float4*)(av + 0) = *(const float4*)&sXT[k][ty * 8 + 0];
            *(float4*)(av + 4) = *(const float4*)&sXT[k][ty * 8 + 4];
            *(float4*)(bv + 0) = *(const float4*)&sW[k][tx * 8 + 0];
            *(float4*)(bv + 4) = *(const float4*)&sW[k][tx * 8 + 4];
#pragma unroll
            for (int i = 0; i < 8; i++)
#pragma unroll
                for (int jj = 0; jj < 8; jj++) acc[i][jj] += av[i] * bv[jj];
        }
        __syncthreads();
    }
#pragma unroll
    for (int i = 0; i < 8; i++) {
        int n = n0 + ty * 8 + i;
        if (n < N_NODES) {
#pragma unroll
            for (int jj = 0; jj < 8; jj++)
                if (RELU) acc[i][jj] = (acc[i][jj] >= 0.f) ? acc[i][jj] : 0.01f * acc[i][jj];
            float4 v0 = make_float4(acc[i][0], acc[i][1], acc[i][2], acc[i][3]);
            float4 v1 = make_float4(acc[i][4], acc[i][5], acc[i][6], acc[i][7]);
            *(float4*)&Z[(size_t)n * OUTF + f0 + tx * 8 + 0] = v0;
            *(float4*)&Z[(size_t)n * OUTF + f0 + tx * 8 + 4] = v1;
        }
    }
}

// small GEMM for layer 2: Z[n, o] = sum_d X[n,d] * W2[d,o], OUTF=16
__global__ void __launch_bounds__(256) k_gemm16(const float* __restrict__ X,
                                                const float* __restrict__ W,
                                                float* __restrict__ Z) {
    constexpr int IN = 256, BM = 64, BK = 16, BN = 16;
    __shared__ float sXT[BK][BM + 4];
    __shared__ float sW[BK][BN + 4];
    int tid = threadIdx.x;
    int tx = tid % 16, ty = tid / 16;
    int n0 = blockIdx.x * BM;
    float acc[4] = {0.f, 0.f, 0.f, 0.f};
    for (int k0 = 0; k0 < IN; k0 += BK) {
        {
            int r = tid >> 2, c4 = (tid & 3) * 4;
            int n = n0 + r;
            float4 v = (n < N_NODES)
                           ? *(const float4*)&X[(size_t)n * IN + k0 + c4]
                           : make_float4(0.f, 0.f, 0.f, 0.f);
            sXT[c4 + 0][r] = v.x;
            sXT[c4 + 1][r] = v.y;
            sXT[c4 + 2][r] = v.z;
            sXT[c4 + 3][r] = v.w;
        }
        if (tid < 64) {
            int kk = tid >> 2, f4 = (tid & 3) * 4;
            *(float4*)&sW[kk][f4] = *(const float4*)&W[(size_t)(k0 + kk) * 16 + f4];
        }
        __syncthreads();
#pragma unroll
        for (int k = 0; k < BK; k++) {
            float w = sW[k][tx];
            float4 a = *(const float4*)&sXT[k][ty * 4];
            acc[0] += a.x * w;
            acc[1] += a.y * w;
            acc[2] += a.z * w;
            acc[3] += a.w * w;
        }
        __syncthreads();
    }
#pragma unroll
    for (int i = 0; i < 4; i++) {
        int n = n0 + ty * 4 + i;
        if (n < N_NODES) Z[(size_t)n * 16 + tx] = acc[i];
    }
}

// warp-per-node aggregation: out[n] = w_self*z[n] + sum_j exp(sim_j*irs)*z[col_j]
template <int OUTF, bool RELU>
__global__ void k_agg(const float* __restrict__ z, float* __restrict__ out) {
    int n = (blockIdx.x * blockDim.x + threadIdx.x) >> 5;
    if (n >= N_NODES) return;
    int lane = threadIdx.x & 31;
    constexpr int FPL = (OUTF >= 32) ? OUTF / 32 : 1;
    float ws = g_wself[n], irs = g_irs[n];
    float acc[FPL];
#pragma unroll
    for (int i = 0; i < FPL; i++) {
        int f = lane + 32 * i;
        acc[i] = (f < OUTF) ? ws * z[(size_t)n * OUTF + f] : 0.0f;
    }
    int b = g_rowptr[n], e2 = g_rowptr[n + 1];
    for (int j = b; j < e2; j++) {
        float s = g_sim[j];
        if (s != 0.0f) {
            float w = expf(s * irs);
            int c = g_ccol[j];
#pragma unroll
            for (int i = 0; i < FPL; i++) {
                int f = lane + 32 * i;
                if (f < OUTF) acc[i] += w * z[(size_t)c * OUTF + f];
            }
        }
    }
#pragma unroll
    for (int i = 0; i < FPL; i++) {
        int f = lane + 32 * i;
        if (f < OUTF) {
            float v = acc[i];
            if (RELU) v = (v >= 0.0f) ? v : 0.01f * v;
            out[(size_t)n * OUTF + f] = v;
        }
    }
}

// ================= driver ====================================================
extern "C" void kernel_launch(void* const* d_in, const int* in_sizes, int n_in,
                              void* d_out, int out_size) {
    const float* x  = (const float*)d_in[0];
    const float* W0 = (const float*)d_in[1];   // [4,128,64]
    const float* W1 = (const float*)d_in[2];   // [4,256,64]
    const float* W2 = (const float*)d_in[3];   // [1,256,16]
    const int*   row = (const int*)d_in[4];
    const int*   col = (const int*)d_in[5];
    float* out = (float*)d_out;

    float *h1, *h2, *z;
    cudaGetSymbolAddress((void**)&h1, g_h1);
    cudaGetSymbolAddress((void**)&h2, g_h2);
    cudaGetSymbolAddress((void**)&z,  g_z);

    const int NODE_WARP_BLOCKS = (N_NODES * 32 + 255) / 256;   // 6250
    const int GEMM_MB = (N_NODES + 127) / 128;                 // 391

    // ---- CSR (shared by all three layers) ----
    k_zero_cnt<<<(N_NODES + 255) / 256, 256>>>();
    k_hist<<<400, 256>>>(row);
    k_scan<<<1, 1024>>>();
    k_scatter<<<400, 256>>>(row, col);

    // ---- layer 0: reassociated ((A+D)x) @ W0, fused leaky-relu ----
    k_norms<128><<<NODE_WARP_BLOCKS, 256>>>(x);
    k_simfused<128><<<NODE_WARP_BLOCKS, 256>>>(x);
    k_agg<128, false><<<NODE_WARP_BLOCKS, 256>>>(x, z);          // z = (A+D)x
    k_gemm8<128, true><<<dim3(GEMM_MB, 4), 128>>>(z, W0, h1, 256);

    // ---- layer 1: h1[50000,256] -> h2[50000,256], relu ----
    k_norms<256><<<NODE_WARP_BLOCKS, 256>>>(h1);
    k_simfused<256><<<NODE_WARP_BLOCKS, 256>>>(h1);
    k_gemm8<256, false><<<dim3(GEMM_MB, 4), 128>>>(h1, W1, z, 256);
    k_agg<256, true><<<NODE_WARP_BLOCKS, 256>>>(z, h2);

    // ---- layer 2: h2[50000,256] -> out[50000,16], no act ----
    k_norms<256><<<NODE_WARP_BLOCKS, 256>>>(h2);
    k_simfused<256><<<NODE_WARP_BLOCKS, 256>>>(h2);
    k_gemm16<<<(N_NODES + 63) / 64, 256>>>(h2, W2, z);
    k_agg<16, false><<<NODE_WARP_BLOCKS, 256>>>(z, out);
}

// round 5
// speedup vs baseline: 1.2312x; 1.2312x over previous
#include <cuda_runtime.h>
#include <math.h>

#define N_NODES 50000
#define N_EDGES 800000

// ---- scratch (device globals; no allocation allowed) ----
__device__ __align__(16) float g_h1[N_NODES * 256];
__device__ __align__(16) float g_h2[N_NODES * 256];
__device__ __align__(16) float g_z [N_NODES * 256];   // also holds layer0's (A+D)x
__device__ float g_sim[N_EDGES];          // CSR order
__device__ int   g_ccol[N_EDGES];         // CSR order: col of slot j
__device__ int   g_crow[N_EDGES];         // CSR order: row of slot j
__device__ float g_rnrm[N_NODES];
__device__ float g_irs[N_NODES];
__device__ float g_wself[N_NODES];
__device__ int   g_rowptr[N_NODES + 1];
__device__ int   g_wr[N_NODES];
__device__ int   g_cnt[N_NODES];

// ================= CSR build (row/col fixed across the 3 layers) =============
__global__ void k_zero_cnt() {
    int i = blockIdx.x * blockDim.x + threadIdx.x;
    if (i < N_NODES) g_cnt[i] = 0;
}

__global__ void k_hist(const int* __restrict__ row) {
    for (int e = blockIdx.x * blockDim.x + threadIdx.x; e < N_EDGES;
         e += gridDim.x * blockDim.x)
        atomicAdd(&g_cnt[row[e]], 1);
}

// single-block exclusive scan over 50000 counts
__global__ void k_scan() {
    __shared__ int wsum[32];
    __shared__ int carry;
    int tid = threadIdx.x, lane = tid & 31, wid = tid >> 5;
    if (tid == 0) carry = 0;
    __syncthreads();
    for (int base = 0; base < N_NODES; base += 1024) {
        int i = base + tid;
        int v = (i < N_NODES) ? g_cnt[i] : 0;
        int inc = v;
#pragma unroll
        for (int o = 1; o < 32; o <<= 1) {
            int y = __shfl_up_sync(0xffffffffu, inc, o);
            if (lane >= o) inc += y;
        }
        if (lane == 31) wsum[wid] = inc;
        __syncthreads();
        if (wid == 0) {
            int w = wsum[lane];
#pragma unroll
            for (int o = 1; o < 32; o <<= 1) {
                int y = __shfl_up_sync(0xffffffffu, w, o);
                if (lane >= o) w += y;
            }
            wsum[lane] = w;
        }
        __syncthreads();
        int pre = (wid > 0) ? wsum[wid - 1] : 0;
        int excl = carry + pre + inc - v;
        if (i < N_NODES) { g_rowptr[i] = excl; g_wr[i] = excl; }
        int chunk_total = wsum[31];
        __syncthreads();
        if (tid == 0) carry += chunk_total;
        __syncthreads();
    }
    if (tid == 0) g_rowptr[N_NODES] = carry;
}

__global__ void k_scatter(const int* __restrict__ row, const int* __restrict__ col) {
    for (int e = blockIdx.x * blockDim.x + threadIdx.x; e < N_EDGES;
         e += gridDim.x * blockDim.x) {
        int r = row[e];
        int p = atomicAdd(&g_wr[r], 1);
        g_ccol[p] = col[e];
        g_crow[p] = r;
    }
}

// ================= per-layer kernels =========================================
// reciprocal node norms
template <int IN>
__global__ void k_norms(const float* __restrict__ x) {
    int n = (blockIdx.x * blockDim.x + threadIdx.x) >> 5;
    if (n >= N_NODES) return;
    int lane = threadIdx.x & 31;
    const float4* xr = (const float4*)(x + (size_t)n * IN);
    float s = 0.0f;
#pragma unroll
    for (int i = 0; i < IN / 128; i++) {
        float4 v = xr[lane + 32 * i];
        s += v.x * v.x + v.y * v.y + v.z * v.z + v.w * v.w;
    }
#pragma unroll
    for (int o = 16; o; o >>= 1) s += __shfl_xor_sync(0xffffffffu, s, o);
    if (lane == 0) g_rnrm[n] = 1.0f / fmaxf(sqrtf(s), 1e-12f);
}

// warp-per-CSR-slot SDDMM: thresholded cosine similarity, CSR-ordered output.
// Consecutive slots share the source row r -> those reads hit L1/L2.
template <int IN>
__global__ void k_sim(const float* __restrict__ x) {
    int j = (blockIdx.x * blockDim.x + threadIdx.x) >> 5;
    if (j >= N_EDGES) return;
    int lane = threadIdx.x & 31;
    int r = g_crow[j], c = g_ccol[j];
    const float4* xa = (const float4*)(x + (size_t)r * IN);
    const float4* xb = (const float4*)(x + (size_t)c * IN);
    float s = 0.0f;
#pragma unroll
    for (int i = 0; i < IN / 128; i++) {
        float4 a = xa[lane + 32 * i];
        float4 b = xb[lane + 32 * i];
        s += a.x * b.x + a.y * b.y + a.z * b.z + a.w * b.w;
    }
#pragma unroll
    for (int o = 16; o; o >>= 1) s += __shfl_xor_sync(0xffffffffu, s, o);
    if (lane == 0) {
        float sim = s * g_rnrm[r] * g_rnrm[c];
        g_sim[j] = (sim < 0.1f) ? 0.0f : sim;
    }
}

// per-node rowsum + degree over contiguous CSR sims
__global__ void k_rowdeg() {
    int n = (blockIdx.x * blockDim.x + threadIdx.x) >> 5;
    if (n >= N_NODES) return;
    int lane = threadIdx.x & 31;
    int b = g_rowptr[n], e2 = g_rowptr[n + 1];
    float s = 0.0f;
    int cnt = 0;
    for (int j = b + lane; j < e2; j += 32) {
        float v = g_sim[j];
        s += v;
        cnt += (v != 0.0f);
    }
#pragma unroll
    for (int o = 16; o; o >>= 1) {
        s += __shfl_xor_sync(0xffffffffu, s, o);
        cnt += __shfl_xor_sync(0xffffffffu, cnt, o);
    }
    if (lane == 0) {
        g_irs[n] = (s > 0.0f) ? (1.0f / s) : 0.0f;
        g_wself[n] = expf(1.0f / (float)(cnt + 1));
    }
}

// ====== 8x8 register-tiled SGEMM, one head per blockIdx.y ======
// Z[n, h*64+o] = sum_d X[n,d] * W[h,d,o]; optional fused leaky-relu.
template <int IN, bool RELU>
__global__ void __launch_bounds__(128) k_gemm8(const float* __restrict__ X,
                                               const float* __restrict__ W,
                                               float* __restrict__ Z,
                                               int OUTF) {
    constexpr int BM = 128, BN = 64, BK = 16;
    __shared__ float sXT[BK][BM + 4];
    __shared__ float sW[BK][BN + 4];
    int tid = threadIdx.x;
    int n0 = blockIdx.x * BM;
    int h = blockIdx.y;
    int f0 = h * BN;
    int tx = tid & 7, ty = tid >> 3;     // 8 x 16
    float acc[8][8];
#pragma unroll
    for (int i = 0; i < 8; i++)
#pragma unroll
        for (int jj = 0; jj < 8; jj++) acc[i][jj] = 0.0f;

    for (int k0 = 0; k0 < IN; k0 += BK) {
        {   // X tile: row tid, 16 d values, transposed
            int n = n0 + tid;
#pragma unroll
            for (int i = 0; i < 4; i++) {
                float4 v = (n < N_NODES)
                               ? *(const float4*)&X[(size_t)n * IN + k0 + i * 4]
                               : make_float4(0.f, 0.f, 0.f, 0.f);
                sXT[i * 4 + 0][tid] = v.x;
                sXT[i * 4 + 1][tid] = v.y;
                sXT[i * 4 + 2][tid] = v.z;
                sXT[i * 4 + 3][tid] = v.w;
            }
        }
        {   // W tile: 16 x 64 = 256 float4 / 128 threads
#pragma unroll
            for (int t = 0; t < 2; t++) {
                int idx = tid + t * 128;
                int kk = idx >> 4, f4 = (idx & 15) * 4;
                *(float4*)&sW[kk][f4] =
                    *(const float4*)&W[((size_t)h * IN + k0 + kk) * 64 + f4];
            }
        }
        __syncthreads();
#pragma unroll
        for (int k = 0; k < BK; k++) {
            float av[8], bv[8];
            *(float4*)(av + 0) = *(const float4*)&sXT[k][ty * 8 + 0];
            *(float4*)(av + 4) = *(const float4*)&sXT[k][ty * 8 + 4];
            *(float4*)(bv + 0) = *(const float4*)&sW[k][tx * 8 + 0];
            *(float4*)(bv + 4) = *(const float4*)&sW[k][tx * 8 + 4];
#pragma unroll
            for (int i = 0; i < 8; i++)
#pragma unroll
                for (int jj = 0; jj < 8; jj++) acc[i][jj] += av[i] * bv[jj];
        }
        __syncthreads();
    }
#pragma unroll
    for (int i = 0; i < 8; i++) {
        int n = n0 + ty * 8 + i;
        if (n < N_NODES) {
#pragma unroll
            for (int jj = 0; jj < 8; jj++)
                if (RELU) acc[i][jj] = (acc[i][jj] >= 0.f) ? acc[i][jj] : 0.01f * acc[i][jj];
            float4 v0 = make_float4(acc[i][0], acc[i][1], acc[i][2], acc[i][3]);
            float4 v1 = make_float4(acc[i][4], acc[i][5], acc[i][6], acc[i][7]);
            *(float4*)&Z[(size_t)n * OUTF + f0 + tx * 8 + 0] = v0;
            *(float4*)&Z[(size_t)n * OUTF + f0 + tx * 8 + 4] = v1;
        }
    }
}

// small GEMM for layer 2: Z[n, o] = sum_d X[n,d] * W2[d,o], OUTF=16
__global__ void __launch_bounds__(256) k_gemm16(const float* __restrict__ X,
                                                const float* __restrict__ W,
                                                float* __restrict__ Z) {
    constexpr int IN = 256, BM = 64, BK = 16, BN = 16;
    __shared__ float sXT[BK][BM + 4];
    __shared__ float sW[BK][BN + 4];
    int tid = threadIdx.x;
    int tx = tid % 16, ty = tid / 16;
    int n0 = blockIdx.x * BM;
    float acc[4] = {0.f, 0.f, 0.f, 0.f};
    for (int k0 = 0; k0 < IN; k0 += BK) {
        {
            int r = tid >> 2, c4 = (tid & 3) * 4;
            int n = n0 + r;
            float4 v = (n < N_NODES)
                           ? *(const float4*)&X[(size_t)n * IN + k0 + c4]
                           : make_float4(0.f, 0.f, 0.f, 0.f);
            sXT[c4 + 0][r] = v.x;
            sXT[c4 + 1][r] = v.y;
            sXT[c4 + 2][r] = v.z;
            sXT[c4 + 3][r] = v.w;
        }
        if (tid < 64) {
            int kk = tid >> 2, f4 = (tid & 3) * 4;
            *(float4*)&sW[kk][f4] = *(const float4*)&W[(size_t)(k0 + kk) * 16 + f4];
        }
        __syncthreads();
#pragma unroll
        for (int k = 0; k < BK; k++) {
            float w = sW[k][tx];
            float4 a = *(const float4*)&sXT[k][ty * 4];
            acc[0] += a.x * w;
            acc[1] += a.y * w;
            acc[2] += a.z * w;
            acc[3] += a.w * w;
        }
        __syncthreads();
    }
#pragma unroll
    for (int i = 0; i < 4; i++) {
        int n = n0 + ty * 4 + i;
        if (n < N_NODES) Z[(size_t)n * 16 + tx] = acc[i];
    }
}

// warp-per-node aggregation, 2-edge unrolled for MLP:
// out[n] = w_self*z[n] + sum_j exp(sim_j*irs)*z[col_j]
template <int OUTF, bool RELU>
__global__ void k_agg(const float* __restrict__ z, float* __restrict__ out) {
    int n = (blockIdx.x * blockDim.x + threadIdx.x) >> 5;
    if (n >= N_NODES) return;
    int lane = threadIdx.x & 31;
    constexpr int FPL = (OUTF >= 32) ? OUTF / 32 : 1;
    float ws = g_wself[n], irs = g_irs[n];
    float acc[FPL];
#pragma unroll
    for (int i = 0; i < FPL; i++) {
        int f = lane + 32 * i;
        acc[i] = (f < OUTF) ? ws * z[(size_t)n * OUTF + f] : 0.0f;
    }
    int b = g_rowptr[n], e2 = g_rowptr[n + 1];
    int j = b;
    for (; j + 2 <= e2; j += 2) {
        float s0 = g_sim[j], s1 = g_sim[j + 1];
        int c0 = g_ccol[j], c1 = g_ccol[j + 1];
        float w0 = (s0 != 0.0f) ? expf(s0 * irs) : 0.0f;
        float w1 = (s1 != 0.0f) ? expf(s1 * irs) : 0.0f;
#pragma unroll
        for (int i = 0; i < FPL; i++) {
            int f = lane + 32 * i;
            if (f < OUTF) {
                float v0 = (s0 != 0.0f) ? z[(size_t)c0 * OUTF + f] : 0.0f;
                float v1 = (s1 != 0.0f) ? z[(size_t)c1 * OUTF + f] : 0.0f;
                acc[i] += w0 * v0 + w1 * v1;
            }
        }
    }
    if (j < e2) {
        float s0 = g_sim[j];
        if (s0 != 0.0f) {
            float w0 = expf(s0 * irs);
            int c0 = g_ccol[j];
#pragma unroll
            for (int i = 0; i < FPL; i++) {
                int f = lane + 32 * i;
                if (f < OUTF) acc[i] += w0 * z[(size_t)c0 * OUTF + f];
            }
        }
    }
#pragma unroll
    for (int i = 0; i < FPL; i++) {
        int f = lane + 32 * i;
        if (f < OUTF) {
            float v = acc[i];
            if (RELU) v = (v >= 0.0f) ? v : 0.01f * v;
            out[(size_t)n * OUTF + f] = v;
        }
    }
}

// ================= driver ====================================================
extern "C" void kernel_launch(void* const* d_in, const int* in_sizes, int n_in,
                              void* d_out, int out_size) {
    const float* x  = (const float*)d_in[0];
    const float* W0 = (const float*)d_in[1];   // [4,128,64]
    const float* W1 = (const float*)d_in[2];   // [4,256,64]
    const float* W2 = (const float*)d_in[3];   // [1,256,16]
    const int*   row = (const int*)d_in[4];
    const int*   col = (const int*)d_in[5];
    float* out = (float*)d_out;

    float *h1, *h2, *z;
    cudaGetSymbolAddress((void**)&h1, g_h1);
    cudaGetSymbolAddress((void**)&h2, g_h2);
    cudaGetSymbolAddress((void**)&z,  g_z);

    const int NODE_WARP_BLOCKS = (N_NODES * 32 + 255) / 256;   // 6250
    const int EDGE_WARP_BLOCKS = (N_EDGES * 32 + 255) / 256;   // 100000
    const int GEMM_MB = (N_NODES + 127) / 128;                 // 391

    // ---- CSR (shared by all three layers) ----
    k_zero_cnt<<<(N_NODES + 255) / 256, 256>>>();
    k_hist<<<400, 256>>>(row);
    k_scan<<<1, 1024>>>();
    k_scatter<<<400, 256>>>(row, col);

    // ---- layer 0: reassociated ((A+D)x) @ W0, fused leaky-relu ----
    k_norms<128><<<NODE_WARP_BLOCKS, 256>>>(x);
    k_sim<128><<<EDGE_WARP_BLOCKS, 256>>>(x);
    k_rowdeg<<<NODE_WARP_BLOCKS, 256>>>();
    k_agg<128, false><<<NODE_WARP_BLOCKS, 256>>>(x, z);          // z = (A+D)x
    k_gemm8<128, true><<<dim3(GEMM_MB, 4), 128>>>(z, W0, h1, 256);

    // ---- layer 1: h1[50000,256] -> h2[50000,256], relu ----
    k_norms<256><<<NODE_WARP_BLOCKS, 256>>>(h1);
    k_sim<256><<<EDGE_WARP_BLOCKS, 256>>>(h1);
    k_rowdeg<<<NODE_WARP_BLOCKS, 256>>>();
    k_gemm8<256, false><<<dim3(GEMM_MB, 4), 128>>>(h1, W1, z, 256);
    k_agg<256, true><<<NODE_WARP_BLOCKS, 256>>>(z, h2);

    // ---- layer 2: h2[50000,256] -> out[50000,16], no act ----
    k_norms<256><<<NODE_WARP_BLOCKS, 256>>>(h2);
    k_sim<256><<<EDGE_WARP_BLOCKS, 256>>>(h2);
    k_rowdeg<<<NODE_WARP_BLOCKS, 256>>>();
    k_gemm16<<<(N_NODES + 63) / 64, 256>>>(h2, W2, z);
    k_agg<16, false><<<NODE_WARP_BLOCKS, 256>>>(z, out);
}

// round 7
// speedup vs baseline: 1.3496x; 1.0962x over previous
#include <cuda_runtime.h>
#include <math.h>

#define N_NODES 50000
#define N_EDGES 800000

// ---- scratch (device globals; no allocation allowed) ----
__device__ __align__(16) float g_h1[N_NODES * 256];
__device__ __align__(16) float g_h2[N_NODES * 256];
__device__ __align__(16) float g_z [N_NODES * 256];   // also holds layer0's (A+D)x
__device__ float g_sim[N_EDGES];          // CSR order, raw thresholded sims
__device__ float g_w  [N_EDGES];          // compacted exp-weights
__device__ int   g_ccol[N_EDGES];         // CSR order: col of slot j
__device__ int   g_ccol2[N_EDGES];        // compacted cols
__device__ int   g_crow[N_EDGES];         // CSR order: row of slot j
__device__ float g_rnrm[N_NODES];
__device__ float g_wself[N_NODES];
__device__ int   g_rowptr[N_NODES + 1];
__device__ int   g_rowend[N_NODES];       // end of compacted segment
__device__ int   g_wr[N_NODES];
__device__ int   g_cnt[N_NODES];

// ================= CSR build (row/col fixed across the 3 layers) =============
__global__ void k_zero_cnt() {
    int i = blockIdx.x * blockDim.x + threadIdx.x;
    if (i < N_NODES) g_cnt[i] = 0;
}

__global__ void k_hist(const int* __restrict__ row) {
    for (int e = blockIdx.x * blockDim.x + threadIdx.x; e < N_EDGES;
         e += gridDim.x * blockDim.x)
        atomicAdd(&g_cnt[row[e]], 1);
}

// single-block exclusive scan over 50000 counts
__global__ void k_scan() {
    __shared__ int wsum[32];
    __shared__ int carry;
    int tid = threadIdx.x, lane = tid & 31, wid = tid >> 5;
    if (tid == 0) carry = 0;
    __syncthreads();
    for (int base = 0; base < N_NODES; base += 1024) {
        int i = base + tid;
        int v = (i < N_NODES) ? g_cnt[i] : 0;
        int inc = v;
#pragma unroll
        for (int o = 1; o < 32; o <<= 1) {
            int y = __shfl_up_sync(0xffffffffu, inc, o);
            if (lane >= o) inc += y;
        }
        if (lane == 31) wsum[wid] = inc;
        __syncthreads();
        if (wid == 0) {
            int w = wsum[lane];
#pragma unroll
            for (int o = 1; o < 32; o <<= 1) {
                int y = __shfl_up_sync(0xffffffffu, w, o);
                if (lane >= o) w += y;
            }
            wsum[lane] = w;
        }
        __syncthreads();
        int pre = (wid > 0) ? wsum[wid - 1] : 0;
        int excl = carry + pre + inc - v;
        if (i < N_NODES) { g_rowptr[i] = excl; g_wr[i] = excl; }
        int chunk_total = wsum[31];
        __syncthreads();
        if (tid == 0) carry += chunk_total;
        __syncthreads();
    }
    if (tid == 0) g_rowptr[N_NODES] = carry;
}

__global__ void k_scatter(const int* __restrict__ row, const int* __restrict__ col) {
    for (int e = blockIdx.x * blockDim.x + threadIdx.x; e < N_EDGES;
         e += gridDim.x * blockDim.x) {
        int r = row[e];
        int p = atomicAdd(&g_wr[r], 1);
        g_ccol[p] = col[e];
        g_crow[p] = r;
    }
}

// ================= per-layer kernels =========================================
// reciprocal node norms
template <int IN>
__global__ void k_norms(const float* __restrict__ x) {
    int n = (blockIdx.x * blockDim.x + threadIdx.x) >> 5;
    if (n >= N_NODES) return;
    int lane = threadIdx.x & 31;
    const float4* xr = (const float4*)(x + (size_t)n * IN);
    float s = 0.0f;
#pragma unroll
    for (int i = 0; i < IN / 128; i++) {
        float4 v = xr[lane + 32 * i];
        s += v.x * v.x + v.y * v.y + v.z * v.z + v.w * v.w;
    }
#pragma unroll
    for (int o = 16; o; o >>= 1) s += __shfl_xor_sync(0xffffffffu, s, o);
    if (lane == 0) g_rnrm[n] = 1.0f / fmaxf(sqrtf(s), 1e-12f);
}

// warp-per-U-CSR-slots SDDMM, loads front-batched for MLP.
template <int IN, int U>
__global__ void k_sim(const float* __restrict__ x) {
    int w = (blockIdx.x * blockDim.x + threadIdx.x) >> 5;
    int j0 = w * U;
    if (j0 >= N_EDGES) return;
    int lane = threadIdx.x & 31;
    constexpr int V = IN / 128;
    int rr[U], cc[U];
#pragma unroll
    for (int u = 0; u < U; u++) {
        int j = j0 + u;
        if (j > N_EDGES - 1) j = N_EDGES - 1;
        rr[u] = g_crow[j];
        cc[u] = g_ccol[j];
    }
    float4 a[U][V], b[U][V];
#pragma unroll
    for (int u = 0; u < U; u++) {
        const float4* xa = (const float4*)(x + (size_t)rr[u] * IN);
        const float4* xb = (const float4*)(x + (size_t)cc[u] * IN);
#pragma unroll
        for (int i = 0; i < V; i++) {
            a[u][i] = xa[lane + 32 * i];
            b[u][i] = xb[lane + 32 * i];
        }
    }
    float s[U];
#pragma unroll
    for (int u = 0; u < U; u++) {
        float t = 0.0f;
#pragma unroll
        for (int i = 0; i < V; i++)
            t += a[u][i].x * b[u][i].x + a[u][i].y * b[u][i].y +
                 a[u][i].z * b[u][i].z + a[u][i].w * b[u][i].w;
        s[u] = t;
    }
#pragma unroll
    for (int o = 16; o; o >>= 1)
#pragma unroll
        for (int u = 0; u < U; u++) s[u] += __shfl_xor_sync(0xffffffffu, s[u], o);
    if (lane == 0) {
#pragma unroll
        for (int u = 0; u < U; u++) {
            int j = j0 + u;
            if (j < N_EDGES) {
                float sim = s[u] * g_rnrm[rr[u]] * g_rnrm[cc[u]];
                g_sim[j] = (sim < 0.1f) ? 0.0f : sim;
            }
        }
    }
}

// rowsum + degree + nonzero compaction + exp-weight precompute (warp per node)
__global__ void k_rowdeg() {
    int n = (blockIdx.x * blockDim.x + threadIdx.x) >> 5;
    if (n >= N_NODES) return;
    int lane = threadIdx.x & 31;
    int b = g_rowptr[n], e2 = g_rowptr[n + 1];
    float s = 0.0f;
    int cnt = 0;
    int wpos = b;
    for (int base = b; base < e2; base += 32) {
        int j = base + lane;
        float v = (j < e2) ? g_sim[j] : 0.0f;
        int c = (j < e2) ? g_ccol[j] : 0;
        bool nz = (v != 0.0f);
        unsigned m = __ballot_sync(0xffffffffu, nz);
        int pos = __popc(m & ((1u << lane) - 1u));
        if (nz) {
            g_w[wpos + pos] = v;
            g_ccol2[wpos + pos] = c;
        }
        s += v;
        cnt += nz;
        wpos += __popc(m);
    }
#pragma unroll
    for (int o = 16; o; o >>= 1) {
        s += __shfl_xor_sync(0xffffffffu, s, o);
        cnt += __shfl_xor_sync(0xffffffffu, cnt, o);
    }
    float irs = (s > 0.0f) ? (1.0f / s) : 0.0f;
    // turn compacted sims into final edge weights
    for (int j = b + lane; j < wpos; j += 32) g_w[j] = __expf(g_w[j] * irs);
    if (lane == 0) {
        g_rowend[n] = wpos;
        g_wself[n] = __expf(1.0f / (float)(cnt + 1));
    }
}

// ====== 8x8 register-tiled SGEMM, one head per blockIdx.y ======
template <int IN, bool RELU>
__global__ void __launch_bounds__(128) k_gemm8(const float* __restrict__ X,
                                               const float* __restrict__ W,
                                               float* __restrict__ Z,
                                               int OUTF) {
    constexpr int BM = 128, BN = 64, BK = 16;
    __shared__ float sXT[BK][BM + 4];
    __shared__ float sW[BK][BN + 4];
    int tid = threadIdx.x;
    int n0 = blockIdx.x * BM;
    int h = blockIdx.y;
    int f0 = h * BN;
    int tx = tid & 7, ty = tid >> 3;
    float acc[8][8];
#pragma unroll
    for (int i = 0; i < 8; i++)
#pragma unroll
        for (int jj = 0; jj < 8; jj++) acc[i][jj] = 0.0f;

    for (int k0 = 0; k0 < IN; k0 += BK) {
        {
            int n = n0 + tid;
#pragma unroll
            for (int i = 0; i < 4; i++) {
                float4 v = (n < N_NODES)
                               ? *(const float4*)&X[(size_t)n * IN + k0 + i * 4]
                               : make_float4(0.f, 0.f, 0.f, 0.f);
                sXT[i * 4 + 0][tid] = v.x;
                sXT[i * 4 + 1][tid] = v.y;
                sXT[i * 4 + 2][tid] = v.z;
                sXT[i * 4 + 3][tid] = v.w;
            }
        }
        {
#pragma unroll
            for (int t = 0; t < 2; t++) {
                int idx = tid + t * 128;
                int kk = idx >> 4, f4 = (idx & 15) * 4;
                *(float4*)&sW[kk][f4] =
                    *(const float4*)&W[((size_t)h * IN + k0 + kk) * 64 + f4];
            }
        }
        __syncthreads();
#pragma unroll
        for (int k = 0; k < BK; k++) {
            float av[8], bv[8];
            *(float4*)(av + 0) = *(const float4*)&sXT[k][ty * 8 + 0];
            *(float4*)(av + 4) = *(const float4*)&sXT[k][ty * 8 + 4];
            *(float4*)(bv + 0) = *(const float4*)&sW[k][tx * 8 + 0];
            *(float4*)(bv + 4) = *(const float4*)&sW[k][tx * 8 + 4];
#pragma unroll
            for (int i = 0; i < 8; i++)
#pragma unroll
                for (int jj = 0; jj < 8; jj++) acc[i][jj] += av[i] * bv[jj];
        }
        __syncthreads();
    }
#pragma unroll
    for (int i = 0; i < 8; i++) {
        int n = n0 + ty * 8 + i;
        if (n < N_NODES) {
#pragma unroll
            for (int jj = 0; jj < 8; jj++)
                if (RELU) acc[i][jj] = (acc[i][jj] >= 0.f) ? acc[i][jj] : 0.01f * acc[i][jj];
            float4 v0 = make_float4(acc[i][0], acc[i][1], acc[i][2], acc[i][3]);
            float4 v1 = make_float4(acc[i][4], acc[i][5], acc[i][6], acc[i][7]);
            *(float4*)&Z[(size_t)n * OUTF + f0 + tx * 8 + 0] = v0;
            *(float4*)&Z[(size_t)n * OUTF + f0 + tx * 8 + 4] = v1;
        }
    }
}

// small GEMM for layer 2: Z[n, o] = sum_d X[n,d] * W2[d,o], OUTF=16
__global__ void __launch_bounds__(256) k_gemm16(const float* __restrict__ X,
                                                const float* __restrict__ W,
                                                float* __restrict__ Z) {
    constexpr int IN = 256, BM = 64, BK = 16;
    __shared__ float sXT[BK][BM + 4];
    __shared__ float sW[BK][16 + 4];
    int tid = threadIdx.x;
    int tx = tid % 16, ty = tid / 16;
    int n0 = blockIdx.x * BM;
    float acc[4] = {0.f, 0.f, 0.f, 0.f};
    for (int k0 = 0; k0 < IN; k0 += BK) {
        {
            int r = tid >> 2, c4 = (tid & 3) * 4;
            int n = n0 + r;
            float4 v = (n < N_NODES)
                           ? *(const float4*)&X[(size_t)n * IN + k0 + c4]
                           : make_float4(0.f, 0.f, 0.f, 0.f);
            sXT[c4 + 0][r] = v.x;
            sXT[c4 + 1][r] = v.y;
            sXT[c4 + 2][r] = v.z;
            sXT[c4 + 3][r] = v.w;
        }
        if (tid < 64) {
            int kk = tid >> 2, f4 = (tid & 3) * 4;
            *(float4*)&sW[kk][f4] = *(const float4*)&W[(size_t)(k0 + kk) * 16 + f4];
        }
        __syncthreads();
#pragma unroll
        for (int k = 0; k < BK; k++) {
            float w = sW[k][tx];
            float4 a = *(const float4*)&sXT[k][ty * 4];
            acc[0] += a.x * w;
            acc[1] += a.y * w;
            acc[2] += a.z * w;
            acc[3] += a.w * w;
        }
        __syncthreads();
    }
#pragma unroll
    for (int i = 0; i < 4; i++) {
        int n = n0 + ty * 4 + i;
        if (n < N_NODES) Z[(size_t)n * 16 + tx] = acc[i];
    }
}

// warp-per-node aggregation over COMPACTED weights, float4 gathers, 2-unrolled.
template <int OUTF, bool RELU>
__global__ void k_agg(const float* __restrict__ z, float* __restrict__ out) {
    int n = (blockIdx.x * blockDim.x + threadIdx.x) >> 5;
    if (n >= N_NODES) return;
    int lane = threadIdx.x & 31;
    constexpr int FV = OUTF / 128;          // float4 per lane (2 for 256, 1 for 128)
    float ws = g_wself[n];
    float4 acc[FV];
    const float4* zn = (const float4*)(z + (size_t)n * OUTF);
#pragma unroll
    for (int i = 0; i < FV; i++) {
        float4 v = zn[lane + 32 * i];
        acc[i] = make_float4(ws * v.x, ws * v.y, ws * v.z, ws * v.w);
    }
    int b = g_rowptr[n], e2 = g_rowend[n];
    int j = b;
    for (; j + 2 <= e2; j += 2) {
        float w0 = g_w[j], w1 = g_w[j + 1];
        int c0 = g_ccol2[j], c1 = g_ccol2[j + 1];
        const float4* z0 = (const float4*)(z + (size_t)c0 * OUTF);
        const float4* z1 = (const float4*)(z + (size_t)c1 * OUTF);
#pragma unroll
        for (int i = 0; i < FV; i++) {
            float4 v0 = z0[lane + 32 * i];
            float4 v1 = z1[lane + 32 * i];
            acc[i].x += w0 * v0.x + w1 * v1.x;
            acc[i].y += w0 * v0.y + w1 * v1.y;
            acc[i].z += w0 * v0.z + w1 * v1.z;
            acc[i].w += w0 * v0.w + w1 * v1.w;
        }
    }
    if (j < e2) {
        float w0 = g_w[j];
        const float4* z0 = (const float4*)(z + (size_t)g_ccol2[j] * OUTF);
#pragma unroll
        for (int i = 0; i < FV; i++) {
            float4 v0 = z0[lane + 32 * i];
            acc[i].x += w0 * v0.x;
            acc[i].y += w0 * v0.y;
            acc[i].z += w0 * v0.z;
            acc[i].w += w0 * v0.w;
        }
    }
#pragma unroll
    for (int i = 0; i < FV; i++) {
        float4 v = acc[i];
        if (RELU) {
            v.x = (v.x >= 0.f) ? v.x : 0.01f * v.x;
            v.y = (v.y >= 0.f) ? v.y : 0.01f * v.y;
            v.z = (v.z >= 0.f) ? v.z : 0.01f * v.z;
            v.w = (v.w >= 0.f) ? v.w : 0.01f * v.w;
        }
        ((float4*)(out + (size_t)n * OUTF))[lane + 32 * i] = v;
    }
}

// 16-wide aggregation: two nodes per warp (half-warp each), compacted weights.
__global__ void k_agg16(const float* __restrict__ z, float* __restrict__ out) {
    int w = (blockIdx.x * blockDim.x + threadIdx.x) >> 5;
    int lane = threadIdx.x & 31;
    int n = w * 2 + (lane >> 4);
    if (n >= N_NODES) return;
    int l = lane & 15;
    float acc = g_wself[n] * z[(size_t)n * 16 + l];
    int b = g_rowptr[n], e2 = g_rowend[n];
    int j = b;
    for (; j + 2 <= e2; j += 2) {
        float w0 = g_w[j], w1 = g_w[j + 1];
        int c0 = g_ccol2[j], c1 = g_ccol2[j + 1];
        acc += w0 * z[(size_t)c0 * 16 + l] + w1 * z[(size_t)c1 * 16 + l];
    }
    if (j < e2) acc += g_w[j] * z[(size_t)g_ccol2[j] * 16 + l];
    out[(size_t)n * 16 + l] = acc;
}

// ================= driver ====================================================
extern "C" void kernel_launch(void* const* d_in, const int* in_sizes, int n_in,
                              void* d_out, int out_size) {
    const float* x  = (const float*)d_in[0];
    const float* W0 = (const float*)d_in[1];   // [4,128,64]
    const float* W1 = (const float*)d_in[2];   // [4,256,64]
    const float* W2 = (const float*)d_in[3];   // [1,256,16]
    const int*   row = (const int*)d_in[4];
    const int*   col = (const int*)d_in[5];
    float* out = (float*)d_out;

    float *h1, *h2, *z;
    cudaGetSymbolAddress((void**)&h1, g_h1);
    cudaGetSymbolAddress((void**)&h2, g_h2);
    cudaGetSymbolAddress((void**)&z,  g_z);

    const int NODE_WARP_BLOCKS = (N_NODES * 32 + 255) / 256;        // 6250
    const int SIM4_BLOCKS = ((N_EDGES + 3) / 4 * 32 + 255) / 256;   // 25000
    const int SIM2_BLOCKS = ((N_EDGES + 1) / 2 * 32 + 255) / 256;   // 50000
    const int GEMM_MB = (N_NODES + 127) / 128;                      // 391

    // ---- CSR (shared by all three layers) ----
    k_zero_cnt<<<(N_NODES + 255) / 256, 256>>>();
    k_hist<<<400, 256>>>(row);
    k_scan<<<1, 1024>>>();
    k_scatter<<<400, 256>>>(row, col);

    // ---- layer 0: reassociated ((A+D)x) @ W0, fused leaky-relu ----
    k_norms<128><<<NODE_WARP_BLOCKS, 256>>>(x);
    k_sim<128, 4><<<SIM4_BLOCKS, 256>>>(x);
    k_rowdeg<<<NODE_WARP_BLOCKS, 256>>>();
    k_agg<128, false><<<NODE_WARP_BLOCKS, 256>>>(x, z);          // z = (A+D)x
    k_gemm8<128, true><<<dim3(GEMM_MB, 4), 128>>>(z, W0, h1, 256);

    // ---- layer 1: h1[50000,256] -> h2[50000,256], relu ----
    k_norms<256><<<NODE_WARP_BLOCKS, 256>>>(h1);
    k_sim<256, 2><<<SIM2_BLOCKS, 256>>>(h1);
    k_rowdeg<<<NODE_WARP_BLOCKS, 256>>>();
    k_gemm8<256, false><<<dim3(GEMM_MB, 4), 128>>>(h1, W1, z, 256);
    k_agg<256, true><<<NODE_WARP_BLOCKS, 256>>>(z, h2);

    // ---- layer 2: h2[50000,256] -> out[50000,16], no act ----
    k_norms<256><<<NODE_WARP_BLOCKS, 256>>>(h2);
    k_sim<256, 2><<<SIM2_BLOCKS, 256>>>(h2);
    k_rowdeg<<<NODE_WARP_BLOCKS, 256>>>();
    k_gemm16<<<(N_NODES + 63) / 64, 256>>>(h2, W2, z);
    k_agg16<<<(N_NODES / 2 * 32 + 255) / 256, 256>>>(z, out);
}